// round 8
// baseline (speedup 1.0000x reference)
#include <cuda_runtime.h>
#include <cuda_fp16.h>
#include <math.h>
#include <stdint.h>

// Problem constants
#define Bq    4
#define Lq    4096
#define Dq    1024
#define Hq    16
#define DHq   64
#define MTOK  (Bq*Lq)      // 16384
#define NQKV  (3*Dq)       // 3072
#define RMSEPS 1.1920929e-07f
#define EPSLIN 1e-06f

// Scratch (device globals — no allocation allowed)
__device__ __align__(256) float g_qkv [(size_t)MTOK * NQKV];
__device__ __align__(256) float g_vkp [16 * 64 * 65 * DHq];
__device__ __align__(256) float g_vk  [64 * 65 * DHq];
__device__ __align__(256) float g_y   [(size_t)MTOK * Dq];
__device__ __align__(256) float g_cos [Lq * 32];
__device__ __align__(256) float g_sin [Lq * 32];
// fp16 operands
__device__ __align__(256) __half g_xh [(size_t)MTOK * Dq];
__device__ __align__(256) __half g_ah [(size_t)MTOK * Dq];   // attn in fp16 (gemm2 A)
__device__ __align__(256) __half g_wh1[(size_t)NQKV * Dq];
__device__ __align__(256) __half g_wh2[(size_t)Dq * Dq];

// ---------------------------------------------------------------------------
__device__ __forceinline__ uint32_t smem_u32(const void* p) {
    uint32_t a;
    asm("{ .reg .u64 t; cvta.to.shared.u64 t, %1; cvt.u32.u64 %0, t; }" : "=r"(a) : "l"(p));
    return a;
}
__device__ __forceinline__ void cp_async16(uint32_t dst, const void* src) {
    asm volatile("cp.async.cg.shared.global [%0], [%1], 16;" :: "r"(dst), "l"(src));
}
#define CP_COMMIT() asm volatile("cp.async.commit_group;" ::: "memory")
template <int N>
__device__ __forceinline__ void cp_wait() {
    asm volatile("cp.async.wait_group %0;" :: "n"(N) : "memory");
}
__device__ __forceinline__ void ldm_x4(uint32_t* r, uint32_t addr) {
    asm volatile("ldmatrix.sync.aligned.m8n8.x4.shared.b16 {%0,%1,%2,%3}, [%4];"
                 : "=r"(r[0]), "=r"(r[1]), "=r"(r[2]), "=r"(r[3]) : "r"(addr));
}
// fp16-accumulator MMA: C(2 regs, packed half2) += A*B
__device__ __forceinline__ void mma_f16acc(uint32_t* c, const uint32_t* a, const uint32_t* b) {
    asm volatile(
        "mma.sync.aligned.m16n8k16.row.col.f16.f16.f16.f16 "
        "{%0,%1}, {%2,%3,%4,%5}, {%6,%7}, {%0,%1};"
        : "+r"(c[0]), "+r"(c[1])
        : "r"(a[0]), "r"(a[1]), "r"(a[2]), "r"(a[3]), "r"(b[0]), "r"(b[1]));
}

// ---------------------------------------------------------------------------
// K0: RoPE tables
// ---------------------------------------------------------------------------
__global__ void rope_tables_k() {
    int idx = blockIdx.x * blockDim.x + threadIdx.x;
    if (idx >= Lq * 32) return;
    int l = idx >> 5, j = idx & 31;
    float inv_freq = expf(-(float)j * (9.210340371976184f / 32.0f));
    float ang = (float)l * inv_freq;
    g_cos[idx] = cosf(ang);
    g_sin[idx] = sinf(ang);
}

// fp32 -> fp16
__global__ __launch_bounds__(256) void to_half_k(
    const float* __restrict__ s, __half* __restrict__ d, int n4)
{
    int i = blockIdx.x * 256 + threadIdx.x;
    if (i >= n4) return;
    float4 v = ((const float4*)s)[i];
    __half2 h0 = __floats2half2_rn(v.x, v.y);
    __half2 h1 = __floats2half2_rn(v.z, v.w);
    ((__half2*)d)[2*i]   = h0;
    ((__half2*)d)[2*i+1] = h1;
}

// ---------------------------------------------------------------------------
// HMMA GEMM v5: C[m,n] = sum_k A[m,k]*B[n,k] + bias[n], K = 1024.
// fp16 MMA with fp16 accumulators, promoted to fp32 every K=64 (2 slabs).
// Tile 128x128, 256 thr (8 warps = 4m x 2n, warp 32x64). 4-stage cp.async.
// ---------------------------------------------------------------------------
#define BKS     32
#define NSLAB   32                  // 1024/32
#define PITCH   80                  // bytes per row (64B data + 16B pad)
#define TILEB   (128 * PITCH)       // 10240
#define OFF_B   TILEB
#define STAGE   (2 * TILEB)         // 20480
#define NSTG    4

__global__ __launch_bounds__(256, 2)
void gemm_hmma3_k(const __half* __restrict__ A, const __half* __restrict__ B,
                  const float* __restrict__ bias, float* __restrict__ C, int N)
{
    extern __shared__ __align__(16) char sm[];
    const uint32_t smb = smem_u32(sm);
    const int tid  = threadIdx.x;
    const int wid  = tid >> 5, lane = tid & 31;
    const int wm   = wid & 3, wn = wid >> 2;
    const int g    = lane >> 2, t = lane & 3;
    const int m0   = blockIdx.y * 128;
    const int n0   = blockIdx.x * 128;

    float acc[2][8][4];
    uint32_t acch[2][8][2];
#pragma unroll
    for (int mf = 0; mf < 2; ++mf)
#pragma unroll
        for (int nf = 0; nf < 8; ++nf) {
#pragma unroll
            for (int e = 0; e < 4; ++e) acc[mf][nf][e] = 0.0f;
            acch[mf][nf][0] = 0u; acch[mf][nf][1] = 0u;
        }

    const int crow = tid >> 2;
    const int c16  = tid & 3;
    auto load_slab = [&](int ks, int st) {
        uint32_t base = smb + st * STAGE;
#pragma unroll
        for (int j = 0; j < 2; ++j) {
            int row = crow + j * 64;
            uint32_t d = base + row * PITCH + c16 * 16;
            cp_async16(d,         A + (size_t)(m0 + row) * 1024 + ks * BKS + c16 * 8);
            cp_async16(d + OFF_B, B + (size_t)(n0 + row) * 1024 + ks * BKS + c16 * 8);
        }
        CP_COMMIT();
    };

    const int quad = lane >> 3, r8 = lane & 7;
    const uint32_t aoff = (uint32_t)((wm * 32 + (quad & 1) * 8 + r8) * PITCH + (quad >> 1) * 16);
    const uint32_t boff = (uint32_t)((wn * 64 + (quad >> 1) * 8 + r8) * PITCH + (quad & 1) * 16);

    load_slab(0, 0);
    load_slab(1, 1);
    load_slab(2, 2);

#pragma unroll 1
    for (int i = 0; i < NSLAB; ++i) {
        cp_wait<2>();
        __syncthreads();
        if (i + 3 < NSLAB) load_slab(i + 3, (i + 3) & 3);
        else CP_COMMIT();
        const uint32_t st = smb + (uint32_t)(i & 3) * STAGE;
#pragma unroll
        for (int kk = 0; kk < 2; ++kk) {
            uint32_t a[2][4];
            ldm_x4(a[0], st + aoff + kk * 32);
            ldm_x4(a[1], st + aoff + kk * 32 + 16 * PITCH);
            const uint32_t bb = st + OFF_B + boff + kk * 32;
#pragma unroll
            for (int nf2 = 0; nf2 < 4; ++nf2) {
                uint32_t b[4];
                ldm_x4(b, bb + nf2 * (16 * PITCH));
                mma_f16acc(acch[0][2*nf2],   a[0], b);
                mma_f16acc(acch[0][2*nf2+1], a[0], b + 2);
                mma_f16acc(acch[1][2*nf2],   a[1], b);
                mma_f16acc(acch[1][2*nf2+1], a[1], b + 2);
            }
        }
        if (i & 1) {   // promote fp16 chunk (K=64) into fp32, reset fp16 acc
#pragma unroll
            for (int mf = 0; mf < 2; ++mf)
#pragma unroll
                for (int nf = 0; nf < 8; ++nf) {
                    float2 lo = __half22float2(*(__half2*)&acch[mf][nf][0]);
                    float2 hi = __half22float2(*(__half2*)&acch[mf][nf][1]);
                    acc[mf][nf][0] += lo.x; acc[mf][nf][1] += lo.y;
                    acc[mf][nf][2] += hi.x; acc[mf][nf][3] += hi.y;
                    acch[mf][nf][0] = 0u;   acch[mf][nf][1] = 0u;
                }
        }
    }

#pragma unroll
    for (int mf = 0; mf < 2; ++mf) {
        int row = m0 + wm * 32 + mf * 16 + g;
#pragma unroll
        for (int nf = 0; nf < 8; ++nf) {
            int col = n0 + wn * 64 + nf * 8 + 2 * t;
            float b0 = bias[col], b1 = bias[col + 1];
            float2 o0 = make_float2(acc[mf][nf][0] + b0, acc[mf][nf][1] + b1);
            float2 o1 = make_float2(acc[mf][nf][2] + b0, acc[mf][nf][3] + b1);
            *(float2*)(C + (size_t)row * N + col)       = o0;
            *(float2*)(C + (size_t)(row + 8) * N + col) = o1;
        }
    }
}

// ---------------------------------------------------------------------------
// K2: per-token rmsnorm(q), rmsnorm(k), RoPE, ReLU — in place in g_qkv.
// ---------------------------------------------------------------------------
__global__ __launch_bounds__(256) void qk_prep_k(const float* __restrict__ gq,
                                                 const float* __restrict__ gk)
{
    const int t = blockIdx.x;
    const int l = t & (Lq - 1);
    const int tid = threadIdx.x;
    float* row = g_qkv + (size_t)t * NQKV;
    float4 q = *(float4*)(row + tid * 4);
    float4 k = *(float4*)(row + Dq + tid * 4);
    float sq = q.x*q.x + q.y*q.y + q.z*q.z + q.w*q.w;
    float sk = k.x*k.x + k.y*k.y + k.z*k.z + k.w*k.w;
#pragma unroll
    for (int o = 16; o > 0; o >>= 1) {
        sq += __shfl_xor_sync(0xffffffffu, sq, o);
        sk += __shfl_xor_sync(0xffffffffu, sk, o);
    }
    __shared__ float wq[8], wk[8];
    __shared__ float bq, bk;
    const int warp = tid >> 5, lane = tid & 31;
    if (lane == 0) { wq[warp] = sq; wk[warp] = sk; }
    __syncthreads();
    if (tid == 0) {
        float aq = 0.0f, ak = 0.0f;
#pragma unroll
        for (int i = 0; i < 8; ++i) { aq += wq[i]; ak += wk[i]; }
        bq = rsqrtf(aq * (1.0f / 1024.0f) + RMSEPS);
        bk = rsqrtf(ak * (1.0f / 1024.0f) + RMSEPS);
    }
    __syncthreads();
    const float scq = bq, sck = bk;
    const int c0 = tid * 4;
    float qe[4] = {q.x, q.y, q.z, q.w};
    float ke[4] = {k.x, k.y, k.z, k.w};
#pragma unroll
    for (int i = 0; i < 4; ++i) {
        qe[i] *= scq * gq[c0 + i];
        ke[i] *= sck * gk[c0 + i];
    }
#pragma unroll
    for (int p = 0; p < 2; ++p) {
        int d = (c0 + 2 * p) & 63;
        int j = d >> 1;
        float c = g_cos[l * 32 + j];
        float s = g_sin[l * 32 + j];
        float q0 = qe[2*p], q1 = qe[2*p + 1];
        qe[2*p]     = q0 * c - q1 * s;
        qe[2*p + 1] = q0 * s + q1 * c;
        float k0 = ke[2*p], k1 = ke[2*p + 1];
        ke[2*p]     = k0 * c - k1 * s;
        ke[2*p + 1] = k0 * s + k1 * c;
    }
    float4 qo = make_float4(fmaxf(qe[0],0.f), fmaxf(qe[1],0.f), fmaxf(qe[2],0.f), fmaxf(qe[3],0.f));
    float4 ko = make_float4(fmaxf(ke[0],0.f), fmaxf(ke[1],0.f), fmaxf(ke[2],0.f), fmaxf(ke[3],0.f));
    *(float4*)(row + tid * 4)      = qo;
    *(float4*)(row + Dq + tid * 4) = ko;
}

// ---------------------------------------------------------------------------
// K3: vk partials, register-tiled. CTA = (b*H+h, Lchunk of 256 tokens).
// ---------------------------------------------------------------------------
__global__ __launch_bounds__(256) void vk_accum_k() {
    const int bh = blockIdx.x;
    const int chunk = blockIdx.y;
    const int b = bh >> 4, h = bh & 15;
    const int tid = threadIdx.x;
    __shared__ __align__(16) float kf_s[32 * 64];
    __shared__ __align__(16) float vp_s[32 * 64];
    const int pq = tid >> 4;
    const int dq = tid & 15;
    float acc[4][4];
    float den[4] = {0.f, 0.f, 0.f, 0.f};
#pragma unroll
    for (int i = 0; i < 4; ++i)
#pragma unroll
        for (int j = 0; j < 4; ++j) acc[i][j] = 0.0f;

    const int tok0 = b * Lq + chunk * 256;
    const int r0 = tid >> 4;
    const int c4 = (tid & 15) << 2;
    for (int sub = 0; sub < 8; ++sub) {
        const int tbase = tok0 + sub * 32;
#pragma unroll
        for (int half = 0; half < 2; ++half) {
            int r = r0 + half * 16;
            const float* src = g_qkv + (size_t)(tbase + r) * NQKV + h * DHq + c4;
            *(float4*)&kf_s[r * 64 + c4] = *(const float4*)(src + Dq);
            *(float4*)&vp_s[r * 64 + c4] = *(const float4*)(src + 2 * Dq);
        }
        __syncthreads();
#pragma unroll 8
        for (int r = 0; r < 32; ++r) {
            float4 vp = *(const float4*)&vp_s[r * 64 + pq * 4];
            float4 kf = *(const float4*)&kf_s[r * 64 + dq * 4];
            const float kfe[4] = {kf.x, kf.y, kf.z, kf.w};
            const float vpe[4] = {vp.x, vp.y, vp.z, vp.w};
#pragma unroll
            for (int i = 0; i < 4; ++i)
#pragma unroll
                for (int j = 0; j < 4; ++j)
                    acc[i][j] = fmaf(vpe[i], kfe[j], acc[i][j]);
            if (pq == 0) {
#pragma unroll
                for (int j = 0; j < 4; ++j) den[j] += kfe[j];
            }
        }
        __syncthreads();
    }
    float* dst = g_vkp + (size_t)chunk * (64 * 65 * 64) + bh * (65 * 64);
#pragma unroll
    for (int i = 0; i < 4; ++i) {
        float4 o = make_float4(acc[i][0], acc[i][1], acc[i][2], acc[i][3]);
        *(float4*)(dst + (pq * 4 + i) * 64 + dq * 4) = o;
    }
    if (pq == 0)
        *(float4*)(dst + 64 * 64 + dq * 4) = make_float4(den[0], den[1], den[2], den[3]);
}

// K4: deterministic reduce of the 16 L-chunk partials.
__global__ void vk_reduce_k() {
    int i = blockIdx.x * 256 + threadIdx.x;
    if (i >= 64 * 65 * 64) return;
    float s = 0.0f;
#pragma unroll
    for (int c = 0; c < 16; ++c) s += g_vkp[(size_t)c * (64 * 65 * 64) + i];
    g_vk[i] = s;
}

// ---------------------------------------------------------------------------
// K5: res = vk . qf ; attn = res[:64]/(res[64]+eps) -> fp16 into g_ah
// den hoisted: computed once per token (not per output dim).
// ---------------------------------------------------------------------------
__global__ __launch_bounds__(256) void attn_apply_k() {
    const int bh = blockIdx.x;
    const int lt = blockIdx.y;
    const int b = bh >> 4, h = bh & 15;
    const int tid = threadIdx.x;
    __shared__ __align__(16) float qf_s[64 * 64];
    __shared__ __align__(16) float vk_s[65 * 65];
    __shared__ float den_s[64];
#pragma unroll
    for (int ei = 0; ei < 17; ++ei) {
        int e = tid + ei * 256;
        if (e < 65 * 64) vk_s[(e >> 6) * 65 + (e & 63)] = g_vk[bh * (65 * 64) + e];
    }
    const int tok0 = b * Lq + lt * 64;
#pragma unroll
    for (int pass = 0; pass < 4; ++pass) {
        int fi = tid + pass * 256;
        int r = fi >> 4, c4 = (fi & 15) << 2;
        float4 v = *(const float4*)(g_qkv + (size_t)(tok0 + r) * NQKV + h * DHq + c4);
        *(float4*)&qf_s[r * 64 + c4] = v;
    }
    __syncthreads();
    if (tid < 64) {        // den for token tid; k-rotation avoids bank conflicts
        float d = 0.0f;
#pragma unroll
        for (int kk = 0; kk < 64; ++kk) {
            int k = (kk + tid) & 63;
            d = fmaf(vk_s[64 * 65 + k], qf_s[tid * 64 + k], d);
        }
        den_s[tid] = d;
    }
    __syncthreads();
    const int dd = tid & 63;
    const int tsub = tid >> 6;
#pragma unroll 4
    for (int it = 0; it < 16; ++it) {
        const int tok = it * 4 + tsub;
        float num = 0.0f;
#pragma unroll
        for (int k = 0; k < 64; ++k)
            num = fmaf(vk_s[dd * 65 + k], qf_s[tok * 64 + k], num);
        float o = num / (den_s[tok] + EPSLIN);
        const int lpos = lt * 64 + tok;
        g_ah[(size_t)(b * Lq + lpos) * Dq + h * DHq + dd] = __float2half_rn(o);
    }
}

// ---------------------------------------------------------------------------
// K7: final rmsnorm over g_y rows -> d_out
// ---------------------------------------------------------------------------
__global__ __launch_bounds__(256) void out_rms_k(const float* __restrict__ gout,
                                                 float* __restrict__ out)
{
    const int t = blockIdx.x;
    const int tid = threadIdx.x;
    const float* row = g_y + (size_t)t * Dq;
    float4 y = *(const float4*)(row + tid * 4);
    float ss = y.x*y.x + y.y*y.y + y.z*y.z + y.w*y.w;
#pragma unroll
    for (int o = 16; o > 0; o >>= 1) ss += __shfl_xor_sync(0xffffffffu, ss, o);
    __shared__ float w[8];
    __shared__ float bsc;
    if ((tid & 31) == 0) w[tid >> 5] = ss;
    __syncthreads();
    if (tid == 0) {
        float a = 0.0f;
#pragma unroll
        for (int i = 0; i < 8; ++i) a += w[i];
        bsc = rsqrtf(a * (1.0f / 1024.0f) + RMSEPS);
    }
    __syncthreads();
    const float sc = bsc;
    const int c0 = tid * 4;
    float4 o4;
    o4.x = y.x * sc * gout[c0 + 0];
    o4.y = y.y * sc * gout[c0 + 1];
    o4.z = y.z * sc * gout[c0 + 2];
    o4.w = y.w * sc * gout[c0 + 3];
    *(float4*)(out + (size_t)t * Dq + c0) = o4;
}

// ---------------------------------------------------------------------------
extern "C" void kernel_launch(void* const* d_in, const int* in_sizes, int n_in,
                              void* d_out, int out_size) {
    (void)in_sizes; (void)n_in; (void)out_size;
    const float* x    = (const float*)d_in[0];
    const float* Wqkv = (const float*)d_in[1];
    const float* bqkv = (const float*)d_in[2];
    const float* gq   = (const float*)d_in[3];
    const float* gk   = (const float*)d_in[4];
    const float* Wout = (const float*)d_in[5];
    const float* bout = (const float*)d_in[6];
    const float* gout = (const float*)d_in[7];
    float* out = (float*)d_out;

    float *qkv_p, *y_p;
    __half *xh, *ah, *wh1, *wh2;
    cudaGetSymbolAddress((void**)&qkv_p, g_qkv);
    cudaGetSymbolAddress((void**)&y_p,   g_y);
    cudaGetSymbolAddress((void**)&xh,  g_xh);
    cudaGetSymbolAddress((void**)&ah,  g_ah);
    cudaGetSymbolAddress((void**)&wh1, g_wh1);
    cudaGetSymbolAddress((void**)&wh2, g_wh2);

    const int DSMEM = NSTG * STAGE;   // 81920
    cudaFuncSetAttribute(gemm_hmma3_k, cudaFuncAttributeMaxDynamicSharedMemorySize, DSMEM);

    rope_tables_k<<<(Lq * 32 + 255) / 256, 256>>>();                          // 0
    to_half_k<<<(MTOK * Dq / 4 + 255) / 256, 256>>>(x, xh, MTOK * Dq / 4);    // 1
    to_half_k<<<(NQKV * Dq / 4 + 255) / 256, 256>>>(Wqkv, wh1, NQKV * Dq / 4);// 2
    gemm_hmma3_k<<<dim3(NQKV / 128, MTOK / 128), 256, DSMEM>>>(               // 3 (profiled slot)
        xh, wh1, bqkv, qkv_p, NQKV);
    to_half_k<<<(Dq * Dq / 4 + 255) / 256, 256>>>(Wout, wh2, Dq * Dq / 4);    // 4
    qk_prep_k<<<MTOK, 256>>>(gq, gk);
    vk_accum_k<<<dim3(64, 16), 256>>>();
    vk_reduce_k<<<(64 * 65 * 64 + 255) / 256, 256>>>();
    attn_apply_k<<<dim3(64, 64), 256>>>();
    gemm_hmma3_k<<<dim3(Dq / 128, MTOK / 128), 256, DSMEM>>>(
        ah, wh2, bout, y_p, Dq);
    out_rms_k<<<MTOK, 256>>>(gout, out);
}

// round 9
// speedup vs baseline: 1.0980x; 1.0980x over previous
#include <cuda_runtime.h>
#include <cuda_fp16.h>
#include <math.h>
#include <stdint.h>

// Problem constants
#define Bq    4
#define Lq    4096
#define Dq    1024
#define Hq    16
#define DHq   64
#define MTOK  (Bq*Lq)      // 16384
#define NQKV  (3*Dq)       // 3072
#define RMSEPS 1.1920929e-07f
#define EPSLIN 1e-06f
#define NCHUNK 8

// Scratch (device globals — no allocation allowed)
__device__ __align__(256) float g_qkv [(size_t)MTOK * NQKV];
__device__ __align__(256) float g_vkp [NCHUNK * 64 * 65 * DHq];
__device__ __align__(256) float g_vk  [64 * 65 * DHq];
__device__ __align__(256) float g_y   [(size_t)MTOK * Dq];
__device__ __align__(256) float g_cos [Lq * 32];
__device__ __align__(256) float g_sin [Lq * 32];
// fp16 operands
__device__ __align__(256) __half g_xh [(size_t)MTOK * Dq];
__device__ __align__(256) __half g_ah [(size_t)MTOK * Dq];   // attn in fp16 (gemm2 A)
__device__ __align__(256) __half g_wh1[(size_t)NQKV * Dq];
__device__ __align__(256) __half g_wh2[(size_t)Dq * Dq];

// ---------------------------------------------------------------------------
__device__ __forceinline__ uint32_t smem_u32(const void* p) {
    uint32_t a;
    asm("{ .reg .u64 t; cvta.to.shared.u64 t, %1; cvt.u32.u64 %0, t; }" : "=r"(a) : "l"(p));
    return a;
}
__device__ __forceinline__ void cp_async16(uint32_t dst, const void* src) {
    asm volatile("cp.async.cg.shared.global [%0], [%1], 16;" :: "r"(dst), "l"(src));
}
#define CP_COMMIT() asm volatile("cp.async.commit_group;" ::: "memory")
template <int N>
__device__ __forceinline__ void cp_wait() {
    asm volatile("cp.async.wait_group %0;" :: "n"(N) : "memory");
}
__device__ __forceinline__ void ldm_x4(uint32_t* r, uint32_t addr) {
    asm volatile("ldmatrix.sync.aligned.m8n8.x4.shared.b16 {%0,%1,%2,%3}, [%4];"
                 : "=r"(r[0]), "=r"(r[1]), "=r"(r[2]), "=r"(r[3]) : "r"(addr));
}
__device__ __forceinline__ void mma_f16(float* c, const uint32_t* a, const uint32_t* b) {
    asm volatile(
        "mma.sync.aligned.m16n8k16.row.col.f32.f16.f16.f32 "
        "{%0,%1,%2,%3}, {%4,%5,%6,%7}, {%8,%9}, {%0,%1,%2,%3};"
        : "+f"(c[0]), "+f"(c[1]), "+f"(c[2]), "+f"(c[3])
        : "r"(a[0]), "r"(a[1]), "r"(a[2]), "r"(a[3]), "r"(b[0]), "r"(b[1]));
}

// ---------------------------------------------------------------------------
// K0: RoPE tables
// ---------------------------------------------------------------------------
__global__ void rope_tables_k() {
    int idx = blockIdx.x * blockDim.x + threadIdx.x;
    if (idx >= Lq * 32) return;
    int l = idx >> 5, j = idx & 31;
    float inv_freq = expf(-(float)j * (9.210340371976184f / 32.0f));
    float ang = (float)l * inv_freq;
    g_cos[idx] = cosf(ang);
    g_sin[idx] = sinf(ang);
}

// fp32 -> fp16
__global__ __launch_bounds__(256) void to_half_k(
    const float* __restrict__ s, __half* __restrict__ d, int n4)
{
    int i = blockIdx.x * 256 + threadIdx.x;
    if (i >= n4) return;
    float4 v = ((const float4*)s)[i];
    __half2 h0 = __floats2half2_rn(v.x, v.y);
    __half2 h1 = __floats2half2_rn(v.z, v.w);
    ((__half2*)d)[2*i]   = h0;
    ((__half2*)d)[2*i+1] = h1;
}

// ---------------------------------------------------------------------------
// HMMA GEMM (R7-proven): C[m,n] = sum_k A[m,k]*B[n,k] + bias[n], K = 1024.
// fp16 MMA, fp32 accumulators. Tile 128x128, 8 warps (4m x 2n, warp 32x64).
// 4-stage cp.async pipeline, load issued before compute, one barrier/slab.
// ---------------------------------------------------------------------------
#define BKS     32
#define NSLAB   32                  // 1024/32
#define PITCH   80                  // bytes per row (64B data + 16B pad)
#define TILEB   (128 * PITCH)       // 10240
#define OFF_B   TILEB
#define STAGE   (2 * TILEB)         // 20480
#define NSTG    4

__global__ __launch_bounds__(256, 2)
void gemm_hmma3_k(const __half* __restrict__ A, const __half* __restrict__ B,
                  const float* __restrict__ bias, float* __restrict__ C, int N)
{
    extern __shared__ __align__(16) char sm[];
    const uint32_t smb = smem_u32(sm);
    const int tid  = threadIdx.x;
    const int wid  = tid >> 5, lane = tid & 31;
    const int wm   = wid & 3, wn = wid >> 2;
    const int g    = lane >> 2, t = lane & 3;
    const int m0   = blockIdx.y * 128;
    const int n0   = blockIdx.x * 128;

    float acc[2][8][4];
#pragma unroll
    for (int mf = 0; mf < 2; ++mf)
#pragma unroll
        for (int nf = 0; nf < 8; ++nf)
#pragma unroll
            for (int e = 0; e < 4; ++e) acc[mf][nf][e] = 0.0f;

    const int crow = tid >> 2;
    const int c16  = tid & 3;
    auto load_slab = [&](int ks, int st) {
        uint32_t base = smb + st * STAGE;
#pragma unroll
        for (int j = 0; j < 2; ++j) {
            int row = crow + j * 64;
            uint32_t d = base + row * PITCH + c16 * 16;
            cp_async16(d,         A + (size_t)(m0 + row) * 1024 + ks * BKS + c16 * 8);
            cp_async16(d + OFF_B, B + (size_t)(n0 + row) * 1024 + ks * BKS + c16 * 8);
        }
        CP_COMMIT();
    };

    const int quad = lane >> 3, r8 = lane & 7;
    const uint32_t aoff = (uint32_t)((wm * 32 + (quad & 1) * 8 + r8) * PITCH + (quad >> 1) * 16);
    const uint32_t boff = (uint32_t)((wn * 64 + (quad >> 1) * 8 + r8) * PITCH + (quad & 1) * 16);

    load_slab(0, 0);
    load_slab(1, 1);
    load_slab(2, 2);

#pragma unroll 1
    for (int i = 0; i < NSLAB; ++i) {
        cp_wait<2>();
        __syncthreads();
        if (i + 3 < NSLAB) load_slab(i + 3, (i + 3) & 3);
        else CP_COMMIT();
        const uint32_t st = smb + (uint32_t)(i & 3) * STAGE;
#pragma unroll
        for (int kk = 0; kk < 2; ++kk) {
            uint32_t a[2][4];
            ldm_x4(a[0], st + aoff + kk * 32);
            ldm_x4(a[1], st + aoff + kk * 32 + 16 * PITCH);
            const uint32_t bb = st + OFF_B + boff + kk * 32;
#pragma unroll
            for (int nf2 = 0; nf2 < 4; ++nf2) {
                uint32_t b[4];
                ldm_x4(b, bb + nf2 * (16 * PITCH));
                mma_f16(acc[0][2*nf2],   a[0], b);
                mma_f16(acc[0][2*nf2+1], a[0], b + 2);
                mma_f16(acc[1][2*nf2],   a[1], b);
                mma_f16(acc[1][2*nf2+1], a[1], b + 2);
            }
        }
    }

#pragma unroll
    for (int mf = 0; mf < 2; ++mf) {
        int row = m0 + wm * 32 + mf * 16 + g;
#pragma unroll
        for (int nf = 0; nf < 8; ++nf) {
            int col = n0 + wn * 64 + nf * 8 + 2 * t;
            float b0 = bias[col], b1 = bias[col + 1];
            float2 o0 = make_float2(acc[mf][nf][0] + b0, acc[mf][nf][1] + b1);
            float2 o1 = make_float2(acc[mf][nf][2] + b0, acc[mf][nf][3] + b1);
            *(float2*)(C + (size_t)row * N + col)       = o0;
            *(float2*)(C + (size_t)(row + 8) * N + col) = o1;
        }
    }
}

// ---------------------------------------------------------------------------
// K2: per-token rmsnorm(q), rmsnorm(k), RoPE, ReLU — in place in g_qkv.
// ---------------------------------------------------------------------------
__global__ __launch_bounds__(256) void qk_prep_k(const float* __restrict__ gq,
                                                 const float* __restrict__ gk)
{
    const int t = blockIdx.x;
    const int l = t & (Lq - 1);
    const int tid = threadIdx.x;
    float* row = g_qkv + (size_t)t * NQKV;
    float4 q = *(float4*)(row + tid * 4);
    float4 k = *(float4*)(row + Dq + tid * 4);
    float sq = q.x*q.x + q.y*q.y + q.z*q.z + q.w*q.w;
    float sk = k.x*k.x + k.y*k.y + k.z*k.z + k.w*k.w;
#pragma unroll
    for (int o = 16; o > 0; o >>= 1) {
        sq += __shfl_xor_sync(0xffffffffu, sq, o);
        sk += __shfl_xor_sync(0xffffffffu, sk, o);
    }
    __shared__ float wq[8], wk[8];
    __shared__ float bq, bk;
    const int warp = tid >> 5, lane = tid & 31;
    if (lane == 0) { wq[warp] = sq; wk[warp] = sk; }
    __syncthreads();
    if (tid == 0) {
        float aq = 0.0f, ak = 0.0f;
#pragma unroll
        for (int i = 0; i < 8; ++i) { aq += wq[i]; ak += wk[i]; }
        bq = rsqrtf(aq * (1.0f / 1024.0f) + RMSEPS);
        bk = rsqrtf(ak * (1.0f / 1024.0f) + RMSEPS);
    }
    __syncthreads();
    const float scq = bq, sck = bk;
    const int c0 = tid * 4;
    float qe[4] = {q.x, q.y, q.z, q.w};
    float ke[4] = {k.x, k.y, k.z, k.w};
#pragma unroll
    for (int i = 0; i < 4; ++i) {
        qe[i] *= scq * gq[c0 + i];
        ke[i] *= sck * gk[c0 + i];
    }
#pragma unroll
    for (int p = 0; p < 2; ++p) {
        int d = (c0 + 2 * p) & 63;
        int j = d >> 1;
        float c = g_cos[l * 32 + j];
        float s = g_sin[l * 32 + j];
        float q0 = qe[2*p], q1 = qe[2*p + 1];
        qe[2*p]     = q0 * c - q1 * s;
        qe[2*p + 1] = q0 * s + q1 * c;
        float k0 = ke[2*p], k1 = ke[2*p + 1];
        ke[2*p]     = k0 * c - k1 * s;
        ke[2*p + 1] = k0 * s + k1 * c;
    }
    float4 qo = make_float4(fmaxf(qe[0],0.f), fmaxf(qe[1],0.f), fmaxf(qe[2],0.f), fmaxf(qe[3],0.f));
    float4 ko = make_float4(fmaxf(ke[0],0.f), fmaxf(ke[1],0.f), fmaxf(ke[2],0.f), fmaxf(ke[3],0.f));
    *(float4*)(row + tid * 4)      = qo;
    *(float4*)(row + Dq + tid * 4) = ko;
}

// ---------------------------------------------------------------------------
// K3: vk partials, register-tiled. CTA = (b*H+h, Lchunk of 512 tokens).
// ---------------------------------------------------------------------------
__global__ __launch_bounds__(256) void vk_accum_k() {
    const int bh = blockIdx.x;
    const int chunk = blockIdx.y;       // 0..NCHUNK-1
    const int b = bh >> 4, h = bh & 15;
    const int tid = threadIdx.x;
    __shared__ __align__(16) float kf_s[32 * 64];
    __shared__ __align__(16) float vp_s[32 * 64];
    const int pq = tid >> 4;
    const int dq = tid & 15;
    float acc[4][4];
    float den[4] = {0.f, 0.f, 0.f, 0.f};
#pragma unroll
    for (int i = 0; i < 4; ++i)
#pragma unroll
        for (int j = 0; j < 4; ++j) acc[i][j] = 0.0f;

    const int tok0 = b * Lq + chunk * (Lq / NCHUNK);
    const int r0 = tid >> 4;
    const int c4 = (tid & 15) << 2;
    for (int sub = 0; sub < (Lq / NCHUNK) / 32; ++sub) {
        const int tbase = tok0 + sub * 32;
#pragma unroll
        for (int half = 0; half < 2; ++half) {
            int r = r0 + half * 16;
            const float* src = g_qkv + (size_t)(tbase + r) * NQKV + h * DHq + c4;
            *(float4*)&kf_s[r * 64 + c4] = *(const float4*)(src + Dq);
            *(float4*)&vp_s[r * 64 + c4] = *(const float4*)(src + 2 * Dq);
        }
        __syncthreads();
#pragma unroll 8
        for (int r = 0; r < 32; ++r) {
            float4 vp = *(const float4*)&vp_s[r * 64 + pq * 4];
            float4 kf = *(const float4*)&kf_s[r * 64 + dq * 4];
            const float kfe[4] = {kf.x, kf.y, kf.z, kf.w};
            const float vpe[4] = {vp.x, vp.y, vp.z, vp.w};
#pragma unroll
            for (int i = 0; i < 4; ++i)
#pragma unroll
                for (int j = 0; j < 4; ++j)
                    acc[i][j] = fmaf(vpe[i], kfe[j], acc[i][j]);
            if (pq == 0) {
#pragma unroll
                for (int j = 0; j < 4; ++j) den[j] += kfe[j];
            }
        }
        __syncthreads();
    }
    float* dst = g_vkp + (size_t)chunk * (64 * 65 * 64) + bh * (65 * 64);
#pragma unroll
    for (int i = 0; i < 4; ++i) {
        float4 o = make_float4(acc[i][0], acc[i][1], acc[i][2], acc[i][3]);
        *(float4*)(dst + (pq * 4 + i) * 64 + dq * 4) = o;
    }
    if (pq == 0)
        *(float4*)(dst + 64 * 64 + dq * 4) = make_float4(den[0], den[1], den[2], den[3]);
}

// K4: deterministic reduce of the NCHUNK partials.
__global__ void vk_reduce_k() {
    int i = blockIdx.x * 256 + threadIdx.x;
    if (i >= 64 * 65 * 64) return;
    float s = 0.0f;
#pragma unroll
    for (int c = 0; c < NCHUNK; ++c) s += g_vkp[(size_t)c * (64 * 65 * 64) + i];
    g_vk[i] = s;
}

// ---------------------------------------------------------------------------
// K5: res = vk . qf ; attn = res[:64]/(res[64]+eps) -> fp16 into g_ah.
// Register-tiled: thread = (dd, tok-group); one vk float4 feeds 16 FMAs,
// qf reads are warp-broadcast. den hoisted per token.
// ---------------------------------------------------------------------------
#define VKP 68   // vk smem pitch (floats): float4-aligned, low-conflict
__global__ __launch_bounds__(256) void attn_apply_k() {
    const int bh = blockIdx.x;
    const int lt = blockIdx.y;
    const int b = bh >> 4, h = bh & 15;
    const int tid = threadIdx.x;
    __shared__ __align__(16) float qf_s[64 * 64];
    __shared__ __align__(16) float vk_s[65 * VKP];
    __shared__ float den_s[64];
#pragma unroll
    for (int ei = 0; ei < 17; ++ei) {
        int e = tid + ei * 256;
        if (e < 65 * 64) vk_s[(e >> 6) * VKP + (e & 63)] = g_vk[bh * (65 * 64) + e];
    }
    const int tok0 = b * Lq + lt * 64;
#pragma unroll
    for (int pass = 0; pass < 4; ++pass) {
        int fi = tid + pass * 256;
        int r = fi >> 4, c4 = (fi & 15) << 2;
        float4 v = *(const float4*)(g_qkv + (size_t)(tok0 + r) * NQKV + h * DHq + c4);
        *(float4*)&qf_s[r * 64 + c4] = v;
    }
    __syncthreads();
    if (tid < 64) {        // den for token tid; k-rotation avoids bank conflicts
        float d = 0.0f;
#pragma unroll
        for (int kk = 0; kk < 64; ++kk) {
            int k = (kk + tid) & 63;
            d = fmaf(vk_s[64 * VKP + k], qf_s[tid * 64 + k], d);
        }
        den_s[tid] = d;
    }
    __syncthreads();
    const int dd  = tid & 63;
    const int grp = tid >> 6;          // warp-uniform (warp = 32 consecutive dd)
    __half* outp = g_ah + (size_t)(b * Lq + lt * 64) * Dq + h * DHq + dd;
#pragma unroll 1
    for (int gi = 0; gi < 4; ++gi) {
        const int tokb = grp * 16 + gi * 4;
        float a0 = 0.f, a1 = 0.f, a2 = 0.f, a3 = 0.f;
#pragma unroll
        for (int k4 = 0; k4 < 16; ++k4) {
            float4 v  = *(const float4*)&vk_s[dd * VKP + k4 * 4];
            float4 q0 = *(const float4*)&qf_s[(tokb + 0) * 64 + k4 * 4];
            float4 q1 = *(const float4*)&qf_s[(tokb + 1) * 64 + k4 * 4];
            float4 q2 = *(const float4*)&qf_s[(tokb + 2) * 64 + k4 * 4];
            float4 q3 = *(const float4*)&qf_s[(tokb + 3) * 64 + k4 * 4];
            a0 = fmaf(v.x, q0.x, a0); a0 = fmaf(v.y, q0.y, a0);
            a0 = fmaf(v.z, q0.z, a0); a0 = fmaf(v.w, q0.w, a0);
            a1 = fmaf(v.x, q1.x, a1); a1 = fmaf(v.y, q1.y, a1);
            a1 = fmaf(v.z, q1.z, a1); a1 = fmaf(v.w, q1.w, a1);
            a2 = fmaf(v.x, q2.x, a2); a2 = fmaf(v.y, q2.y, a2);
            a2 = fmaf(v.z, q2.z, a2); a2 = fmaf(v.w, q2.w, a2);
            a3 = fmaf(v.x, q3.x, a3); a3 = fmaf(v.y, q3.y, a3);
            a3 = fmaf(v.z, q3.z, a3); a3 = fmaf(v.w, q3.w, a3);
        }
        outp[(size_t)(tokb + 0) * Dq] = __float2half_rn(a0 / (den_s[tokb + 0] + EPSLIN));
        outp[(size_t)(tokb + 1) * Dq] = __float2half_rn(a1 / (den_s[tokb + 1] + EPSLIN));
        outp[(size_t)(tokb + 2) * Dq] = __float2half_rn(a2 / (den_s[tokb + 2] + EPSLIN));
        outp[(size_t)(tokb + 3) * Dq] = __float2half_rn(a3 / (den_s[tokb + 3] + EPSLIN));
    }
}

// ---------------------------------------------------------------------------
// K7: final rmsnorm over g_y rows -> d_out
// ---------------------------------------------------------------------------
__global__ __launch_bounds__(256) void out_rms_k(const float* __restrict__ gout,
                                                 float* __restrict__ out)
{
    const int t = blockIdx.x;
    const int tid = threadIdx.x;
    const float* row = g_y + (size_t)t * Dq;
    float4 y = *(const float4*)(row + tid * 4);
    float ss = y.x*y.x + y.y*y.y + y.z*y.z + y.w*y.w;
#pragma unroll
    for (int o = 16; o > 0; o >>= 1) ss += __shfl_xor_sync(0xffffffffu, ss, o);
    __shared__ float w[8];
    __shared__ float bsc;
    if ((tid & 31) == 0) w[tid >> 5] = ss;
    __syncthreads();
    if (tid == 0) {
        float a = 0.0f;
#pragma unroll
        for (int i = 0; i < 8; ++i) a += w[i];
        bsc = rsqrtf(a * (1.0f / 1024.0f) + RMSEPS);
    }
    __syncthreads();
    const float sc = bsc;
    const int c0 = tid * 4;
    float4 o4;
    o4.x = y.x * sc * gout[c0 + 0];
    o4.y = y.y * sc * gout[c0 + 1];
    o4.z = y.z * sc * gout[c0 + 2];
    o4.w = y.w * sc * gout[c0 + 3];
    *(float4*)(out + (size_t)t * Dq + c0) = o4;
}

// ---------------------------------------------------------------------------
extern "C" void kernel_launch(void* const* d_in, const int* in_sizes, int n_in,
                              void* d_out, int out_size) {
    (void)in_sizes; (void)n_in; (void)out_size;
    const float* x    = (const float*)d_in[0];
    const float* Wqkv = (const float*)d_in[1];
    const float* bqkv = (const float*)d_in[2];
    const float* gq   = (const float*)d_in[3];
    const float* gk   = (const float*)d_in[4];
    const float* Wout = (const float*)d_in[5];
    const float* bout = (const float*)d_in[6];
    const float* gout = (const float*)d_in[7];
    float* out = (float*)d_out;

    float *qkv_p, *y_p;
    __half *xh, *ah, *wh1, *wh2;
    cudaGetSymbolAddress((void**)&qkv_p, g_qkv);
    cudaGetSymbolAddress((void**)&y_p,   g_y);
    cudaGetSymbolAddress((void**)&xh,  g_xh);
    cudaGetSymbolAddress((void**)&ah,  g_ah);
    cudaGetSymbolAddress((void**)&wh1, g_wh1);
    cudaGetSymbolAddress((void**)&wh2, g_wh2);

    const int DSMEM = NSTG * STAGE;   // 81920
    cudaFuncSetAttribute(gemm_hmma3_k, cudaFuncAttributeMaxDynamicSharedMemorySize, DSMEM);

    rope_tables_k<<<(Lq * 32 + 255) / 256, 256>>>();                          // 0
    to_half_k<<<(MTOK * Dq / 4 + 255) / 256, 256>>>(x, xh, MTOK * Dq / 4);    // 1
    to_half_k<<<(NQKV * Dq / 4 + 255) / 256, 256>>>(Wqkv, wh1, NQKV * Dq / 4);// 2
    gemm_hmma3_k<<<dim3(NQKV / 128, MTOK / 128), 256, DSMEM>>>(               // 3 (profiled slot)
        xh, wh1, bqkv, qkv_p, NQKV);
    to_half_k<<<(Dq * Dq / 4 + 255) / 256, 256>>>(Wout, wh2, Dq * Dq / 4);    // 4
    qk_prep_k<<<MTOK, 256>>>(gq, gk);
    vk_accum_k<<<dim3(64, NCHUNK), 256>>>();
    vk_reduce_k<<<(64 * 65 * 64 + 255) / 256, 256>>>();
    attn_apply_k<<<dim3(64, 64), 256>>>();
    gemm_hmma3_k<<<dim3(Dq / 128, MTOK / 128), 256, DSMEM>>>(
        ah, wh2, bout, y_p, Dq);
    out_rms_k<<<MTOK, 256>>>(gout, out);
}